// round 3
// baseline (speedup 1.0000x reference)
#include <cuda_runtime.h>
#include <math.h>

#define THREADS 256
#define NWARPS 8
#define EPW 4
#define DIMX 160
#define EPSF 1e-5f
#define INV_SQ3 0.57735026918962576451f

#define MAX_NODES 50000
#define MAX_ACT 200000

// ---------- scratch (static device arrays) ----------
__device__ float g_nf[MAX_NODES * DIMX];     // normalized node features
__device__ float g_ms[MAX_ACT * 64];         // silu(o_s[:64])
__device__ float g_mv[MAX_ACT * 96];         // gated o_v, layout [e][3*o + c]
__device__ float g_lat_in[MAX_ACT * 232];    // [oh_i(4) | lat_n(128) | o_s(96) | oh_j(4)]
__device__ float g_hid[MAX_ACT * 256];       // silu(lat_in @ W_lat1)

__device__ __forceinline__ float wsum(float v) {
#pragma unroll
    for (int o = 16; o > 0; o >>= 1) v += __shfl_xor_sync(0xffffffffu, v, o);
    return v;
}
__device__ __forceinline__ float sigm(float x) { return 1.f / (1.f + expf(-x)); }
__device__ __forceinline__ float4 ld4(const float* p) { return *reinterpret_cast<const float4*>(p); }
__device__ __forceinline__ void fma4(float& a, float4 x, float4 w) {
    a = fmaf(x.x, w.x, a); a = fmaf(x.y, w.y, a); a = fmaf(x.z, w.z, a); a = fmaf(x.w, w.w, a);
}

// ===================== K1: node SLN (one warp per node) =====================
__global__ void k_node_norm(const float* __restrict__ nf, const float* __restrict__ gs,
                            const float* __restrict__ bs, const float* __restrict__ gv,
                            int n_nodes) {
    int w = (blockIdx.x * THREADS + threadIdx.x) >> 5;
    int l = threadIdx.x & 31;
    if (w >= n_nodes) return;
    const float* r = nf + (size_t)w * DIMX;
    float s0 = r[l], s1 = r[32 + l];
    float mu = wsum(s0 + s1) * (1.f / 64.f);
    float m2 = wsum(s0 * s0 + s1 * s1) * (1.f / 64.f);
    float rsv = rsqrtf(m2 - mu * mu + EPSF);
    float v0 = r[64 + 3 * l], v1 = r[65 + 3 * l], v2 = r[66 + 3 * l];
    float rmi = rsqrtf(wsum(v0 * v0 + v1 * v1 + v2 * v2) * (1.f / 32.f) + EPSF);
    float* o = g_nf + (size_t)w * DIMX;
    o[l] = (s0 - mu) * rsv * gs[l] + bs[l];
    o[32 + l] = (s1 - mu) * rsv * gs[32 + l] + bs[32 + l];
    float gk = gv[l] * rmi;
    o[64 + 3 * l] = v0 * gk; o[65 + 3 * l] = v1 * gk; o[66 + 3 * l] = v2 * gk;
}

// ===================== K2: gather + edge SLN + tensor product =====================
// smem: WaT[96][196] WbT[96][100] WcT[32][196] WdT[32][100] + staging[8][4][576]
// staging per edge: sA[192] | vA 3 planes x 96 | u[96]
#define SMEM_A ((96*196 + 96*100 + 32*196 + 32*100 + NWARPS*EPW*576) * 4)
__global__ __launch_bounds__(THREADS, 1) void k_edge_a(
    const float* __restrict__ ef, const float* __restrict__ esh,
    const int* __restrict__ eidx, const int* __restrict__ act,
    const float* __restrict__ onehot,
    const float* __restrict__ egs, const float* __restrict__ ebs, const float* __restrict__ egv,
    const float* __restrict__ Wa, const float* __restrict__ Wb,
    const float* __restrict__ Wc, const float* __restrict__ Wd,
    int n_act, int n_edges) {
    extern __shared__ float sm[];
    float* WaT = sm;
    float* WbT = WaT + 96 * 196;
    float* WcT = WbT + 96 * 100;
    float* WdT = WcT + 32 * 196;
    float* STG = WdT + 32 * 100;
    int tid = threadIdx.x;
    for (int i = tid; i < 192 * 96; i += THREADS) WaT[(i % 96) * 196 + i / 96] = Wa[i];
    for (int i = tid; i < 96 * 96; i += THREADS)  WbT[(i % 96) * 100 + i / 96] = Wb[i];
    for (int i = tid; i < 192 * 32; i += THREADS) WcT[(i % 32) * 196 + i / 32] = Wc[i];
    for (int i = tid; i < 96 * 32; i += THREADS)  WdT[(i % 32) * 100 + i / 32] = Wd[i];
    __syncthreads();
    int wq = tid >> 5, l = tid & 31;
    float* ST = STG + wq * (EPW * 576);
    int gw = blockIdx.x * NWARPS + wq;
    int stride = gridDim.x * NWARPS * EPW;
    for (int eb = gw * EPW; eb < n_act; eb += stride) {
        float sh0r[EPW], s10[EPW], s11[EPW], s12[EPW];
        int inode[EPW], jnode[EPW];
#pragma unroll
        for (int e = 0; e < EPW; e++) {
            int ec = eb + e; if (ec >= n_act) ec = n_act - 1;
            int ae = act[ec];
            int ii = eidx[ae], jj = eidx[n_edges + ae];
            inode[e] = ii; jnode[e] = jj;
            float* sA = ST + e * 576;
            float* vA = sA + 192;
            float* u = sA + 480;
            const float* ri = g_nf + (size_t)ii * DIMX;
            sA[l] = ri[l]; sA[32 + l] = ri[32 + l];
            vA[l] = ri[64 + 3 * l]; vA[96 + l] = ri[65 + 3 * l]; vA[192 + l] = ri[66 + 3 * l];
            const float* rj = g_nf + (size_t)jj * DIMX;
            sA[128 + l] = rj[l]; sA[160 + l] = rj[32 + l];
            vA[64 + l] = rj[64 + 3 * l]; vA[160 + l] = rj[65 + 3 * l]; vA[256 + l] = rj[66 + 3 * l];
            const float* re = ef + (size_t)ec * DIMX;
            float s0 = re[l], s1 = re[32 + l];
            float mu = wsum(s0 + s1) * (1.f / 64.f);
            float m2 = wsum(s0 * s0 + s1 * s1) * (1.f / 64.f);
            float rsv = rsqrtf(m2 - mu * mu + EPSF);
            sA[64 + l] = (s0 - mu) * rsv * egs[l] + ebs[l];
            sA[96 + l] = (s1 - mu) * rsv * egs[32 + l] + ebs[32 + l];
            float v0 = re[64 + 3 * l], v1 = re[65 + 3 * l], v2 = re[66 + 3 * l];
            float rmi = rsqrtf(wsum(v0 * v0 + v1 * v1 + v2 * v2) * (1.f / 32.f) + EPSF);
            float gk = egv[l] * rmi;
            vA[32 + l] = v0 * gk; vA[128 + l] = v1 * gk; vA[224 + l] = v2 * gk;
            const float* sp = esh + (size_t)ec * 4;
            sh0r[e] = sp[0]; s10[e] = sp[1]; s11[e] = sp[2]; s12[e] = sp[3];
#pragma unroll
            for (int t = 0; t < 3; t++) {  // u[k] uses only this lane's own staged values
                int k = l + 32 * t;
                u[k] = (vA[k] * s10[e] + vA[96 + k] * s11[e] + vA[192 + k] * s12[e]) * INV_SQ3;
            }
        }
        __syncwarp();
        // o_s channels l, l+32, l+64:  sh0*(sA@Wa) + u@Wb
        float aA[3][EPW], aB[3][EPW];
#pragma unroll
        for (int j = 0; j < 3; j++)
#pragma unroll
            for (int e = 0; e < EPW; e++) { aA[j][e] = 0.f; aB[j][e] = 0.f; }
        for (int k = 0; k < 192; k += 4) {
            float4 w0 = ld4(&WaT[l * 196 + k]);
            float4 w1 = ld4(&WaT[(l + 32) * 196 + k]);
            float4 w2 = ld4(&WaT[(l + 64) * 196 + k]);
#pragma unroll
            for (int e = 0; e < EPW; e++) {
                float4 x = ld4(&ST[e * 576 + k]);
                fma4(aA[0][e], x, w0); fma4(aA[1][e], x, w1); fma4(aA[2][e], x, w2);
            }
        }
        for (int k = 0; k < 96; k += 4) {
            float4 w0 = ld4(&WbT[l * 100 + k]);
            float4 w1 = ld4(&WbT[(l + 32) * 100 + k]);
            float4 w2 = ld4(&WbT[(l + 64) * 100 + k]);
#pragma unroll
            for (int e = 0; e < EPW; e++) {
                float4 x = ld4(&ST[e * 576 + 480 + k]);
                fma4(aB[0][e], x, w0); fma4(aB[1][e], x, w1); fma4(aB[2][e], x, w2);
            }
        }
        float os[3][EPW];
#pragma unroll
        for (int j = 0; j < 3; j++)
#pragma unroll
            for (int e = 0; e < EPW; e++) os[j][e] = fmaf(sh0r[e], aA[j][e], aB[j][e]);
        // swc (channel l) and wd[c] (channel l, 3 components)
        float swc[EPW], wd[3][EPW];
#pragma unroll
        for (int e = 0; e < EPW; e++) { swc[e] = 0.f; wd[0][e] = 0.f; wd[1][e] = 0.f; wd[2][e] = 0.f; }
        for (int k = 0; k < 192; k += 4) {
            float4 w = ld4(&WcT[l * 196 + k]);
#pragma unroll
            for (int e = 0; e < EPW; e++) { float4 x = ld4(&ST[e * 576 + k]); fma4(swc[e], x, w); }
        }
        for (int k = 0; k < 96; k += 4) {
            float4 w = ld4(&WdT[l * 100 + k]);
#pragma unroll
            for (int e = 0; e < EPW; e++) {
#pragma unroll
                for (int c = 0; c < 3; c++) {
                    float4 x = ld4(&ST[e * 576 + 192 + 96 * c + k]);
                    fma4(wd[c][e], x, w);
                }
            }
        }
#pragma unroll
        for (int e = 0; e < EPW; e++) {
            int eg = eb + e;
            if (eg < n_act) {
                float gate = sigm(os[2][e]);
                g_ms[(size_t)eg * 64 + l] = os[0][e] * sigm(os[0][e]);
                g_ms[(size_t)eg * 64 + 32 + l] = os[1][e] * sigm(os[1][e]);
                float s1c[3] = { s10[e], s11[e], s12[e] };
#pragma unroll
                for (int c = 0; c < 3; c++) {
                    float ov = fmaf(swc[e], s1c[c], wd[c][e] * sh0r[e]);
                    g_mv[(size_t)eg * 96 + 3 * l + c] = ov * gate;
                }
                float* li = g_lat_in + (size_t)eg * 232;
                li[132 + l] = os[0][e]; li[164 + l] = os[1][e]; li[196 + l] = os[2][e];
                if (l < 4) { li[l] = onehot[inode[e] * 4 + l]; li[228 + l] = onehot[jnode[e] * 4 + l]; }
            }
        }
        __syncwarp();
    }
}

// ===================== K2b: W_edge / Wp / Wres + latent LN + edge_out =====================
// staging per edge (448): lat[128] | ms[64] | mv 3x32 (c-major) | rs[64] | rv 3x32
#define SMEM_B ((96*132 + 64*68 + 32*36 + 64*68 + 32*36 + NWARPS*EPW*448) * 4)
__global__ __launch_bounds__(THREADS, 1) void k_edge_b(
    const float* __restrict__ latents, const float* __restrict__ ef,
    const int* __restrict__ act,
    const float* __restrict__ lg, const float* __restrict__ lb,
    const float* __restrict__ We, const float* __restrict__ Wps, const float* __restrict__ Wpv,
    const float* __restrict__ Wrs, const float* __restrict__ Wrv,
    float* __restrict__ out_edge, int n_act) {
    extern __shared__ float sm[];
    float* WeT = sm;
    float* WpsT = WeT + 96 * 132;
    float* WpvT = WpsT + 64 * 68;
    float* WrsT = WpvT + 32 * 36;
    float* WrvT = WrsT + 64 * 68;
    float* STG = WrvT + 32 * 36;
    int tid = threadIdx.x;
    for (int i = tid; i < 128 * 96; i += THREADS) WeT[(i % 96) * 132 + i / 96] = We[i];
    for (int i = tid; i < 64 * 64; i += THREADS)  WpsT[(i % 64) * 68 + i / 64] = Wps[i];
    for (int i = tid; i < 32 * 32; i += THREADS)  WpvT[(i % 32) * 36 + i / 32] = Wpv[i];
    for (int i = tid; i < 64 * 64; i += THREADS)  WrsT[(i % 64) * 68 + i / 64] = Wrs[i];
    for (int i = tid; i < 32 * 32; i += THREADS)  WrvT[(i % 32) * 36 + i / 32] = Wrv[i];
    __syncthreads();
    int wq = tid >> 5, l = tid & 31;
    float* ST = STG + wq * (EPW * 448);
    int gw = blockIdx.x * NWARPS + wq;
    int stride = gridDim.x * NWARPS * EPW;
    for (int eb = gw * EPW; eb < n_act; eb += stride) {
#pragma unroll
        for (int e = 0; e < EPW; e++) {
            int ec = eb + e; if (ec >= n_act) ec = n_act - 1;
            int ae = act[ec];
            float* S = ST + e * 448;
            const float* la = latents + (size_t)ae * 128;
            float x0 = la[l], x1 = la[32 + l], x2 = la[64 + l], x3 = la[96 + l];
            S[l] = x0; S[32 + l] = x1; S[64 + l] = x2; S[96 + l] = x3;
            float mu = wsum(x0 + x1 + x2 + x3) * (1.f / 128.f);
            float m2 = wsum(x0 * x0 + x1 * x1 + x2 * x2 + x3 * x3) * (1.f / 128.f);
            float rsv = rsqrtf(m2 - mu * mu + EPSF);
            int eg = eb + e;
            if (eg < n_act) {
                float* li = g_lat_in + (size_t)eg * 232 + 4;
                li[l] = (x0 - mu) * rsv * lg[l] + lb[l];
                li[32 + l] = (x1 - mu) * rsv * lg[32 + l] + lb[32 + l];
                li[64 + l] = (x2 - mu) * rsv * lg[64 + l] + lb[64 + l];
                li[96 + l] = (x3 - mu) * rsv * lg[96 + l] + lb[96 + l];
            }
            const float* ms = g_ms + (size_t)ec * 64;
            S[128 + l] = ms[l]; S[160 + l] = ms[32 + l];
            const float* mv = g_mv + (size_t)ec * 96;
            S[192 + l] = mv[3 * l]; S[224 + l] = mv[3 * l + 1]; S[256 + l] = mv[3 * l + 2];
            const float* re = ef + (size_t)ec * DIMX;
            S[288 + l] = re[l]; S[320 + l] = re[32 + l];
            S[352 + l] = re[64 + 3 * l]; S[384 + l] = re[65 + 3 * l]; S[416 + l] = re[66 + 3 * l];
        }
        __syncwarp();
        float ww[3][EPW], ps[2][EPW], rs[2][EPW], pv[3][EPW], rv[3][EPW];
#pragma unroll
        for (int e = 0; e < EPW; e++) {
            ww[0][e] = ww[1][e] = ww[2][e] = 0.f;
            ps[0][e] = ps[1][e] = rs[0][e] = rs[1][e] = 0.f;
            pv[0][e] = pv[1][e] = pv[2][e] = rv[0][e] = rv[1][e] = rv[2][e] = 0.f;
        }
        for (int k = 0; k < 128; k += 4) {
            float4 w0 = ld4(&WeT[l * 132 + k]);
            float4 w1 = ld4(&WeT[(l + 32) * 132 + k]);
            float4 w2 = ld4(&WeT[(l + 64) * 132 + k]);
#pragma unroll
            for (int e = 0; e < EPW; e++) {
                float4 x = ld4(&ST[e * 448 + k]);
                fma4(ww[0][e], x, w0); fma4(ww[1][e], x, w1); fma4(ww[2][e], x, w2);
            }
        }
        for (int k = 0; k < 64; k += 4) {
            float4 p0 = ld4(&WpsT[l * 68 + k]);
            float4 p1 = ld4(&WpsT[(l + 32) * 68 + k]);
            float4 r0 = ld4(&WrsT[l * 68 + k]);
            float4 r1 = ld4(&WrsT[(l + 32) * 68 + k]);
#pragma unroll
            for (int e = 0; e < EPW; e++) {
                float4 xm = ld4(&ST[e * 448 + 128 + k]);
                float4 xr = ld4(&ST[e * 448 + 288 + k]);
                fma4(ps[0][e], xm, p0); fma4(ps[1][e], xm, p1);
                fma4(rs[0][e], xr, r0); fma4(rs[1][e], xr, r1);
            }
        }
        for (int k = 0; k < 32; k += 4) {
            float4 pw = ld4(&WpvT[l * 36 + k]);
            float4 rw = ld4(&WrvT[l * 36 + k]);
#pragma unroll
            for (int e = 0; e < EPW; e++) {
#pragma unroll
                for (int c = 0; c < 3; c++) {
                    float4 xm = ld4(&ST[e * 448 + 192 + 32 * c + k]);
                    float4 xr = ld4(&ST[e * 448 + 352 + 32 * c + k]);
                    fma4(pv[c][e], xm, pw); fma4(rv[c][e], xr, rw);
                }
            }
        }
#pragma unroll
        for (int e = 0; e < EPW; e++) {
            int eg = eb + e;
            if (eg < n_act) {
                float* oe = out_edge + (size_t)eg * DIMX;
                oe[l] = fmaf(ps[0][e], ww[0][e], rs[0][e]);
                oe[32 + l] = fmaf(ps[1][e], ww[1][e], rs[1][e]);
#pragma unroll
                for (int c = 0; c < 3; c++)
                    oe[64 + 3 * l + c] = fmaf(pv[c][e], ww[2][e], rv[c][e]);
            }
        }
        __syncwarp();
    }
}

// ===================== K3: hid = silu(lat_in @ W_lat1), N split by blockIdx.y =====================
#define SMEM_1 ((128*236 + NWARPS*EPW*232) * 4)
__global__ __launch_bounds__(THREADS, 1) void k_lat1(const float* __restrict__ W1, int n_act) {
    extern __shared__ float sm[];
    float* WT = sm;
    float* STG = WT + 128 * 236;
    int tid = threadIdx.x;
    int base = blockIdx.y * 128;
    for (int i = tid; i < 232 * 128; i += THREADS) {
        int oo = i % 128, k = i / 128;
        WT[oo * 236 + k] = W1[k * 256 + base + oo];
    }
    __syncthreads();
    int wq = tid >> 5, l = tid & 31;
    float* ST = STG + wq * (EPW * 232);
    int gw = blockIdx.x * NWARPS + wq;
    int stride = gridDim.x * NWARPS * EPW;
    for (int eb = gw * EPW; eb < n_act; eb += stride) {
#pragma unroll
        for (int e = 0; e < EPW; e++) {
            int ec = eb + e; if (ec >= n_act) ec = n_act - 1;
            const float* li = g_lat_in + (size_t)ec * 232;
            for (int k = l; k < 232; k += 32) ST[e * 232 + k] = li[k];
        }
        __syncwarp();
        float acc[4][EPW];
#pragma unroll
        for (int m = 0; m < 4; m++)
#pragma unroll
            for (int e = 0; e < EPW; e++) acc[m][e] = 0.f;
        for (int k = 0; k < 232; k += 4) {
            float4 w0 = ld4(&WT[l * 236 + k]);
            float4 w1 = ld4(&WT[(l + 32) * 236 + k]);
            float4 w2 = ld4(&WT[(l + 64) * 236 + k]);
            float4 w3 = ld4(&WT[(l + 96) * 236 + k]);
#pragma unroll
            for (int e = 0; e < EPW; e++) {
                float4 x = ld4(&ST[e * 232 + k]);
                fma4(acc[0][e], x, w0); fma4(acc[1][e], x, w1);
                fma4(acc[2][e], x, w2); fma4(acc[3][e], x, w3);
            }
        }
#pragma unroll
        for (int e = 0; e < EPW; e++) {
            int eg = eb + e;
            if (eg < n_act) {
                float* h = g_hid + (size_t)eg * 256 + base;
#pragma unroll
                for (int m = 0; m < 4; m++) {
                    float v = acc[m][e];
                    h[l + 32 * m] = v * sigm(v);
                }
            }
        }
        __syncwarp();
    }
}

// ===================== K4: new_lat = (hid @ W_lat2) * cutoff[ae] -> scatter =====================
#define SMEM_2 ((128*260 + NWARPS*EPW*256) * 4)
__global__ __launch_bounds__(THREADS, 1) void k_lat2(
    const float* __restrict__ W2, const int* __restrict__ act,
    const float* __restrict__ cutoff, float* __restrict__ out_lat, int n_act) {
    extern __shared__ float sm[];
    float* WT = sm;
    float* STG = WT + 128 * 260;
    int tid = threadIdx.x;
    for (int i = tid; i < 256 * 128; i += THREADS)
        WT[(i % 128) * 260 + i / 128] = W2[i];
    __syncthreads();
    int wq = tid >> 5, l = tid & 31;
    float* ST = STG + wq * (EPW * 256);
    int gw = blockIdx.x * NWARPS + wq;
    int stride = gridDim.x * NWARPS * EPW;
    for (int eb = gw * EPW; eb < n_act; eb += stride) {
#pragma unroll
        for (int e = 0; e < EPW; e++) {
            int ec = eb + e; if (ec >= n_act) ec = n_act - 1;
            const float* h = g_hid + (size_t)ec * 256;
#pragma unroll
            for (int j = 0; j < 8; j++) ST[e * 256 + l + 32 * j] = h[l + 32 * j];
        }
        __syncwarp();
        float acc[4][EPW];
#pragma unroll
        for (int m = 0; m < 4; m++)
#pragma unroll
            for (int e = 0; e < EPW; e++) acc[m][e] = 0.f;
        for (int k = 0; k < 256; k += 4) {
            float4 w0 = ld4(&WT[l * 260 + k]);
            float4 w1 = ld4(&WT[(l + 32) * 260 + k]);
            float4 w2 = ld4(&WT[(l + 64) * 260 + k]);
            float4 w3 = ld4(&WT[(l + 96) * 260 + k]);
#pragma unroll
            for (int e = 0; e < EPW; e++) {
                float4 x = ld4(&ST[e * 256 + k]);
                fma4(acc[0][e], x, w0); fma4(acc[1][e], x, w1);
                fma4(acc[2][e], x, w2); fma4(acc[3][e], x, w3);
            }
        }
#pragma unroll
        for (int e = 0; e < EPW; e++) {
            int eg = eb + e;
            if (eg < n_act) {
                int ae = act[eg];
                float cc = cutoff[ae];
                float* ol = out_lat + (size_t)ae * 128;
#pragma unroll
                for (int m = 0; m < 4; m++) ol[l + 32 * m] = acc[m][e] * cc;
            }
        }
        __syncwarp();
    }
}

// ===================== launcher =====================
extern "C" void kernel_launch(void* const* d_in, const int* in_sizes, int n_in,
                              void* d_out, int out_size) {
    const float* latents   = (const float*)d_in[0];
    const float* node_feat = (const float*)d_in[1];
    const float* onehot    = (const float*)d_in[2];
    const float* edge_feat = (const float*)d_in[3];
    const float* edge_sh   = (const float*)d_in[4];
    const int*   edge_idx  = (const int*)d_in[5];
    const float* cutoff    = (const float*)d_in[6];
    const int*   act       = (const int*)d_in[7];
    const float* n_gs = (const float*)d_in[8];
    const float* n_bs = (const float*)d_in[9];
    const float* n_gv = (const float*)d_in[10];
    const float* e_gs = (const float*)d_in[11];
    const float* e_bs = (const float*)d_in[12];
    const float* e_gv = (const float*)d_in[13];
    const float* lg   = (const float*)d_in[14];
    const float* lb   = (const float*)d_in[15];
    const float* Wa   = (const float*)d_in[16];
    const float* Wb   = (const float*)d_in[17];
    const float* Wc   = (const float*)d_in[18];
    const float* Wd   = (const float*)d_in[19];
    const float* Wps  = (const float*)d_in[20];
    const float* Wpv  = (const float*)d_in[21];
    const float* We   = (const float*)d_in[22];
    const float* W1   = (const float*)d_in[23];
    const float* W2   = (const float*)d_in[24];
    const float* Wrs  = (const float*)d_in[25];
    const float* Wrv  = (const float*)d_in[26];

    int n_nodes = in_sizes[1] / DIMX;
    int n_act   = in_sizes[7];
    int n_edges = in_sizes[6];

    float* out_edge = (float*)d_out;
    float* out_lat  = out_edge + (size_t)n_act * DIMX;

    cudaFuncSetAttribute(k_edge_a, cudaFuncAttributeMaxDynamicSharedMemorySize, SMEM_A);
    cudaFuncSetAttribute(k_edge_b, cudaFuncAttributeMaxDynamicSharedMemorySize, SMEM_B);
    cudaFuncSetAttribute(k_lat1,   cudaFuncAttributeMaxDynamicSharedMemorySize, SMEM_1);
    cudaFuncSetAttribute(k_lat2,   cudaFuncAttributeMaxDynamicSharedMemorySize, SMEM_2);

    cudaMemcpyAsync(out_lat, latents, (size_t)n_edges * 128 * sizeof(float),
                    cudaMemcpyDeviceToDevice, 0);

    int nb1 = (n_nodes * 32 + THREADS - 1) / THREADS;
    k_node_norm<<<nb1, THREADS>>>(node_feat, n_gs, n_bs, n_gv, n_nodes);

    k_edge_a<<<148, THREADS, SMEM_A>>>(edge_feat, edge_sh, edge_idx, act, onehot,
                                       e_gs, e_bs, e_gv, Wa, Wb, Wc, Wd, n_act, n_edges);

    k_edge_b<<<148, THREADS, SMEM_B>>>(latents, edge_feat, act, lg, lb,
                                       We, Wps, Wpv, Wrs, Wrv, out_edge, n_act);

    k_lat1<<<dim3(148, 2), THREADS, SMEM_1>>>(W1, n_act);

    k_lat2<<<148, THREADS, SMEM_2>>>(W2, act, cutoff, out_lat, n_act);
}

// round 4
// speedup vs baseline: 1.2827x; 1.2827x over previous
#include <cuda_runtime.h>
#include <math.h>

#define DIMX 160
#define EPSF 1e-5f
#define INV_SQ3 0.57735026918962576451f

#define MAX_NODES 50000
#define MAX_ACT 200000

// ---------- scratch (static device arrays) ----------
__device__ float g_nf[MAX_NODES * DIMX];     // normalized node features
__device__ float g_ms[MAX_ACT * 64];         // silu(o_s[:64])
__device__ float g_mv[MAX_ACT * 96];         // gated o_v, layout [e][3*o + c]
__device__ float g_lat_in[MAX_ACT * 232];    // [oh_i(4) | lat_n(128) | o_s(96) | oh_j(4)]
__device__ float g_hid[MAX_ACT * 256];       // silu(lat_in @ W_lat1)

typedef unsigned long long u64;

__device__ __forceinline__ float wsum(float v) {
#pragma unroll
    for (int o = 16; o > 0; o >>= 1) v += __shfl_xor_sync(0xffffffffu, v, o);
    return v;
}
__device__ __forceinline__ float sigm(float x) { return 1.f / (1.f + expf(-x)); }
__device__ __forceinline__ void ffma2(u64& a, u64 x, u64 w) {
    asm("fma.rn.f32x2 %0, %1, %2, %0;" : "+l"(a) : "l"(x), "l"(w));
}
__device__ __forceinline__ float hadd2(u64 a) {
    return __uint_as_float((unsigned)a) + __uint_as_float((unsigned)(a >> 32));
}
__device__ __forceinline__ ulonglong2 ld2(const float* p) {
    return *reinterpret_cast<const ulonglong2*>(p);
}

// ===================== K1: node SLN (one warp per node) =====================
__global__ void k_node_norm(const float* __restrict__ nf, const float* __restrict__ gs,
                            const float* __restrict__ bs, const float* __restrict__ gv,
                            int n_nodes) {
    int w = (blockIdx.x * 256 + threadIdx.x) >> 5;
    int l = threadIdx.x & 31;
    if (w >= n_nodes) return;
    const float* r = nf + (size_t)w * DIMX;
    float s0 = r[l], s1 = r[32 + l];
    float mu = wsum(s0 + s1) * (1.f / 64.f);
    float m2 = wsum(s0 * s0 + s1 * s1) * (1.f / 64.f);
    float rsv = rsqrtf(m2 - mu * mu + EPSF);
    float v0 = r[64 + 3 * l], v1 = r[65 + 3 * l], v2 = r[66 + 3 * l];
    float rmi = rsqrtf(wsum(v0 * v0 + v1 * v1 + v2 * v2) * (1.f / 32.f) + EPSF);
    float* o = g_nf + (size_t)w * DIMX;
    o[l] = (s0 - mu) * rsv * gs[l] + bs[l];
    o[32 + l] = (s1 - mu) * rsv * gs[32 + l] + bs[32 + l];
    float gk = gv[l] * rmi;
    o[64 + 3 * l] = v0 * gk; o[65 + 3 * l] = v1 * gk; o[66 + 3 * l] = v2 * gk;
}

// ===================== K2a: gather + edge SLN + tensor product (Wa,Wb,Wc,Wd) =====================
// 256 threads, 8 warps, EPW=4. staging per edge: sA[192] | vA 3x96 | u[96] = 576
#define EA_T 256
#define EA_W 8
#define EA_E 4
#define SMEM_A ((96*196 + 96*100 + 32*196 + 32*100 + EA_W*EA_E*576) * 4)
__global__ __launch_bounds__(EA_T, 1) void k_edge_a(
    const float* __restrict__ ef, const float* __restrict__ esh,
    const int* __restrict__ eidx, const int* __restrict__ act,
    const float* __restrict__ onehot,
    const float* __restrict__ egs, const float* __restrict__ ebs, const float* __restrict__ egv,
    const float* __restrict__ Wa, const float* __restrict__ Wb,
    const float* __restrict__ Wc, const float* __restrict__ Wd,
    int n_act, int n_edges) {
    extern __shared__ float sm[];
    float* WaT = sm;
    float* WbT = WaT + 96 * 196;
    float* WcT = WbT + 96 * 100;
    float* WdT = WcT + 32 * 196;
    float* STG = WdT + 32 * 100;
    int tid = threadIdx.x;
    for (int i = tid; i < 192 * 96; i += EA_T) WaT[(i % 96) * 196 + i / 96] = Wa[i];
    for (int i = tid; i < 96 * 96; i += EA_T)  WbT[(i % 96) * 100 + i / 96] = Wb[i];
    for (int i = tid; i < 192 * 32; i += EA_T) WcT[(i % 32) * 196 + i / 32] = Wc[i];
    for (int i = tid; i < 96 * 32; i += EA_T)  WdT[(i % 32) * 100 + i / 32] = Wd[i];
    __syncthreads();
    int wq = tid >> 5, l = tid & 31;
    float* ST = STG + wq * (EA_E * 576);
    int gw = blockIdx.x * EA_W + wq;
    int stride = gridDim.x * EA_W * EA_E;
    for (int eb = gw * EA_E; eb < n_act; eb += stride) {
        float sh0r[EA_E], s10[EA_E], s11[EA_E], s12[EA_E];
        int inode[EA_E], jnode[EA_E];
#pragma unroll
        for (int e = 0; e < EA_E; e++) {
            int ec = eb + e; if (ec >= n_act) ec = n_act - 1;
            int ae = act[ec];
            int ii = eidx[ae], jj = eidx[n_edges + ae];
            inode[e] = ii; jnode[e] = jj;
            float* sA = ST + e * 576;
            float* vA = sA + 192;
            float* u = sA + 480;
            const float* ri = g_nf + (size_t)ii * DIMX;
            sA[l] = ri[l]; sA[32 + l] = ri[32 + l];
            vA[l] = ri[64 + 3 * l]; vA[96 + l] = ri[65 + 3 * l]; vA[192 + l] = ri[66 + 3 * l];
            const float* rj = g_nf + (size_t)jj * DIMX;
            sA[128 + l] = rj[l]; sA[160 + l] = rj[32 + l];
            vA[64 + l] = rj[64 + 3 * l]; vA[160 + l] = rj[65 + 3 * l]; vA[256 + l] = rj[66 + 3 * l];
            const float* re = ef + (size_t)ec * DIMX;
            float s0 = re[l], s1 = re[32 + l];
            float mu = wsum(s0 + s1) * (1.f / 64.f);
            float m2 = wsum(s0 * s0 + s1 * s1) * (1.f / 64.f);
            float rsv = rsqrtf(m2 - mu * mu + EPSF);
            sA[64 + l] = (s0 - mu) * rsv * egs[l] + ebs[l];
            sA[96 + l] = (s1 - mu) * rsv * egs[32 + l] + ebs[32 + l];
            float v0 = re[64 + 3 * l], v1 = re[65 + 3 * l], v2 = re[66 + 3 * l];
            float rmi = rsqrtf(wsum(v0 * v0 + v1 * v1 + v2 * v2) * (1.f / 32.f) + EPSF);
            float gk = egv[l] * rmi;
            vA[32 + l] = v0 * gk; vA[128 + l] = v1 * gk; vA[224 + l] = v2 * gk;
            const float* sp = esh + (size_t)ec * 4;
            sh0r[e] = sp[0]; s10[e] = sp[1]; s11[e] = sp[2]; s12[e] = sp[3];
#pragma unroll
            for (int t = 0; t < 3; t++) {
                int k = l + 32 * t;
                u[k] = (vA[k] * s10[e] + vA[96 + k] * s11[e] + vA[192 + k] * s12[e]) * INV_SQ3;
            }
        }
        __syncwarp();
        // o_s = sh0*(sA@Wa) + u@Wb for channels l, l+32, l+64
        u64 aA[3][EA_E];
#pragma unroll
        for (int j = 0; j < 3; j++)
#pragma unroll
            for (int e = 0; e < EA_E; e++) aA[j][e] = 0ull;
        for (int k = 0; k < 192; k += 4) {
            ulonglong2 w0 = ld2(&WaT[l * 196 + k]);
            ulonglong2 w1 = ld2(&WaT[(l + 32) * 196 + k]);
            ulonglong2 w2 = ld2(&WaT[(l + 64) * 196 + k]);
#pragma unroll
            for (int e = 0; e < EA_E; e++) {
                ulonglong2 x = ld2(&ST[e * 576 + k]);
                ffma2(aA[0][e], x.x, w0.x); ffma2(aA[0][e], x.y, w0.y);
                ffma2(aA[1][e], x.x, w1.x); ffma2(aA[1][e], x.y, w1.y);
                ffma2(aA[2][e], x.x, w2.x); ffma2(aA[2][e], x.y, w2.y);
            }
        }
        float fA[3][EA_E];
#pragma unroll
        for (int j = 0; j < 3; j++)
#pragma unroll
            for (int e = 0; e < EA_E; e++) fA[j][e] = hadd2(aA[j][e]);
        u64 aB[3][EA_E];
#pragma unroll
        for (int j = 0; j < 3; j++)
#pragma unroll
            for (int e = 0; e < EA_E; e++) aB[j][e] = 0ull;
        for (int k = 0; k < 96; k += 4) {
            ulonglong2 w0 = ld2(&WbT[l * 100 + k]);
            ulonglong2 w1 = ld2(&WbT[(l + 32) * 100 + k]);
            ulonglong2 w2 = ld2(&WbT[(l + 64) * 100 + k]);
#pragma unroll
            for (int e = 0; e < EA_E; e++) {
                ulonglong2 x = ld2(&ST[e * 576 + 480 + k]);
                ffma2(aB[0][e], x.x, w0.x); ffma2(aB[0][e], x.y, w0.y);
                ffma2(aB[1][e], x.x, w1.x); ffma2(aB[1][e], x.y, w1.y);
                ffma2(aB[2][e], x.x, w2.x); ffma2(aB[2][e], x.y, w2.y);
            }
        }
        float os[3][EA_E];
#pragma unroll
        for (int j = 0; j < 3; j++)
#pragma unroll
            for (int e = 0; e < EA_E; e++) os[j][e] = fmaf(sh0r[e], fA[j][e], hadd2(aB[j][e]));
        // swc (channel l) and wd[c] (channel l, 3 comps)
        u64 swc[EA_E], wd[3][EA_E];
#pragma unroll
        for (int e = 0; e < EA_E; e++) { swc[e] = 0ull; wd[0][e] = 0ull; wd[1][e] = 0ull; wd[2][e] = 0ull; }
        for (int k = 0; k < 192; k += 4) {
            ulonglong2 w = ld2(&WcT[l * 196 + k]);
#pragma unroll
            for (int e = 0; e < EA_E; e++) {
                ulonglong2 x = ld2(&ST[e * 576 + k]);
                ffma2(swc[e], x.x, w.x); ffma2(swc[e], x.y, w.y);
            }
        }
        for (int k = 0; k < 96; k += 4) {
            ulonglong2 w = ld2(&WdT[l * 100 + k]);
#pragma unroll
            for (int e = 0; e < EA_E; e++) {
#pragma unroll
                for (int c = 0; c < 3; c++) {
                    ulonglong2 x = ld2(&ST[e * 576 + 192 + 96 * c + k]);
                    ffma2(wd[c][e], x.x, w.x); ffma2(wd[c][e], x.y, w.y);
                }
            }
        }
#pragma unroll
        for (int e = 0; e < EA_E; e++) {
            int eg = eb + e;
            if (eg < n_act) {
                float gate = sigm(os[2][e]);
                g_ms[(size_t)eg * 64 + l] = os[0][e] * sigm(os[0][e]);
                g_ms[(size_t)eg * 64 + 32 + l] = os[1][e] * sigm(os[1][e]);
                float s1c[3] = { s10[e], s11[e], s12[e] };
                float sw = hadd2(swc[e]);
#pragma unroll
                for (int c = 0; c < 3; c++) {
                    float ov = fmaf(sw, s1c[c], hadd2(wd[c][e]) * sh0r[e]);
                    g_mv[(size_t)eg * 96 + 3 * l + c] = ov * gate;
                }
                float* li = g_lat_in + (size_t)eg * 232;
                li[132 + l] = os[0][e]; li[164 + l] = os[1][e]; li[196 + l] = os[2][e];
                if (l < 4) { li[l] = onehot[inode[e] * 4 + l]; li[228 + l] = onehot[jnode[e] * 4 + l]; }
            }
        }
        __syncwarp();
    }
}

// ===================== K2b: W_edge / Wp / Wres + latent LN + edge_out =====================
// 512 threads, 16 warps, EPW=4. staging per edge (448): lat[128]|ms[64]|mv 3x32|rs[64]|rv 3x32
#define EB_T 512
#define EB_W 16
#define EB_E 4
#define SMEM_B ((96*132 + 64*68 + 32*36 + 64*68 + 32*36 + EB_W*EB_E*448) * 4)
__global__ __launch_bounds__(EB_T, 1) void k_edge_b(
    const float* __restrict__ latents, const float* __restrict__ ef,
    const int* __restrict__ act,
    const float* __restrict__ lg, const float* __restrict__ lb,
    const float* __restrict__ We, const float* __restrict__ Wps, const float* __restrict__ Wpv,
    const float* __restrict__ Wrs, const float* __restrict__ Wrv,
    float* __restrict__ out_edge, int n_act) {
    extern __shared__ float sm[];
    float* WeT = sm;
    float* WpsT = WeT + 96 * 132;
    float* WpvT = WpsT + 64 * 68;
    float* WrsT = WpvT + 32 * 36;
    float* WrvT = WrsT + 64 * 68;
    float* STG = WrvT + 32 * 36;
    int tid = threadIdx.x;
    for (int i = tid; i < 128 * 96; i += EB_T) WeT[(i % 96) * 132 + i / 96] = We[i];
    for (int i = tid; i < 64 * 64; i += EB_T)  WpsT[(i % 64) * 68 + i / 64] = Wps[i];
    for (int i = tid; i < 32 * 32; i += EB_T)  WpvT[(i % 32) * 36 + i / 32] = Wpv[i];
    for (int i = tid; i < 64 * 64; i += EB_T)  WrsT[(i % 64) * 68 + i / 64] = Wrs[i];
    for (int i = tid; i < 32 * 32; i += EB_T)  WrvT[(i % 32) * 36 + i / 32] = Wrv[i];
    __syncthreads();
    int wq = tid >> 5, l = tid & 31;
    float* ST = STG + wq * (EB_E * 448);
    int gw = blockIdx.x * EB_W + wq;
    int stride = gridDim.x * EB_W * EB_E;
    for (int eb = gw * EB_E; eb < n_act; eb += stride) {
#pragma unroll
        for (int e = 0; e < EB_E; e++) {
            int ec = eb + e; if (ec >= n_act) ec = n_act - 1;
            int ae = act[ec];
            float* S = ST + e * 448;
            const float* la = latents + (size_t)ae * 128;
            float x0 = la[l], x1 = la[32 + l], x2 = la[64 + l], x3 = la[96 + l];
            S[l] = x0; S[32 + l] = x1; S[64 + l] = x2; S[96 + l] = x3;
            float mu = wsum(x0 + x1 + x2 + x3) * (1.f / 128.f);
            float m2 = wsum(x0 * x0 + x1 * x1 + x2 * x2 + x3 * x3) * (1.f / 128.f);
            float rsv = rsqrtf(m2 - mu * mu + EPSF);
            int eg = eb + e;
            if (eg < n_act) {
                float* li = g_lat_in + (size_t)eg * 232 + 4;
                li[l] = (x0 - mu) * rsv * lg[l] + lb[l];
                li[32 + l] = (x1 - mu) * rsv * lg[32 + l] + lb[32 + l];
                li[64 + l] = (x2 - mu) * rsv * lg[64 + l] + lb[64 + l];
                li[96 + l] = (x3 - mu) * rsv * lg[96 + l] + lb[96 + l];
            }
            const float* ms = g_ms + (size_t)ec * 64;
            S[128 + l] = ms[l]; S[160 + l] = ms[32 + l];
            const float* mv = g_mv + (size_t)ec * 96;
            S[192 + l] = mv[3 * l]; S[224 + l] = mv[3 * l + 1]; S[256 + l] = mv[3 * l + 2];
            const float* re = ef + (size_t)ec * DIMX;
            S[288 + l] = re[l]; S[320 + l] = re[32 + l];
            S[352 + l] = re[64 + 3 * l]; S[384 + l] = re[65 + 3 * l]; S[416 + l] = re[66 + 3 * l];
        }
        __syncwarp();
        u64 ww[3][EB_E];
#pragma unroll
        for (int j = 0; j < 3; j++)
#pragma unroll
            for (int e = 0; e < EB_E; e++) ww[j][e] = 0ull;
        for (int k = 0; k < 128; k += 4) {
            ulonglong2 w0 = ld2(&WeT[l * 132 + k]);
            ulonglong2 w1 = ld2(&WeT[(l + 32) * 132 + k]);
            ulonglong2 w2 = ld2(&WeT[(l + 64) * 132 + k]);
#pragma unroll
            for (int e = 0; e < EB_E; e++) {
                ulonglong2 x = ld2(&ST[e * 448 + k]);
                ffma2(ww[0][e], x.x, w0.x); ffma2(ww[0][e], x.y, w0.y);
                ffma2(ww[1][e], x.x, w1.x); ffma2(ww[1][e], x.y, w1.y);
                ffma2(ww[2][e], x.x, w2.x); ffma2(ww[2][e], x.y, w2.y);
            }
        }
        float fw[3][EB_E];
#pragma unroll
        for (int j = 0; j < 3; j++)
#pragma unroll
            for (int e = 0; e < EB_E; e++) fw[j][e] = hadd2(ww[j][e]);
        u64 ps[2][EB_E], rs[2][EB_E];
#pragma unroll
        for (int e = 0; e < EB_E; e++) { ps[0][e] = ps[1][e] = rs[0][e] = rs[1][e] = 0ull; }
        for (int k = 0; k < 64; k += 4) {
            ulonglong2 p0 = ld2(&WpsT[l * 68 + k]);
            ulonglong2 p1 = ld2(&WpsT[(l + 32) * 68 + k]);
            ulonglong2 r0 = ld2(&WrsT[l * 68 + k]);
            ulonglong2 r1 = ld2(&WrsT[(l + 32) * 68 + k]);
#pragma unroll
            for (int e = 0; e < EB_E; e++) {
                ulonglong2 xm = ld2(&ST[e * 448 + 128 + k]);
                ulonglong2 xr = ld2(&ST[e * 448 + 288 + k]);
                ffma2(ps[0][e], xm.x, p0.x); ffma2(ps[0][e], xm.y, p0.y);
                ffma2(ps[1][e], xm.x, p1.x); ffma2(ps[1][e], xm.y, p1.y);
                ffma2(rs[0][e], xr.x, r0.x); ffma2(rs[0][e], xr.y, r0.y);
                ffma2(rs[1][e], xr.x, r1.x); ffma2(rs[1][e], xr.y, r1.y);
            }
        }
        float fps[2][EB_E], frs[2][EB_E];
#pragma unroll
        for (int j = 0; j < 2; j++)
#pragma unroll
            for (int e = 0; e < EB_E; e++) { fps[j][e] = hadd2(ps[j][e]); frs[j][e] = hadd2(rs[j][e]); }
        u64 pv[3][EB_E], rv[3][EB_E];
#pragma unroll
        for (int c = 0; c < 3; c++)
#pragma unroll
            for (int e = 0; e < EB_E; e++) { pv[c][e] = 0ull; rv[c][e] = 0ull; }
        for (int k = 0; k < 32; k += 4) {
            ulonglong2 pw = ld2(&WpvT[l * 36 + k]);
            ulonglong2 rw = ld2(&WrvT[l * 36 + k]);
#pragma unroll
            for (int e = 0; e < EB_E; e++) {
#pragma unroll
                for (int c = 0; c < 3; c++) {
                    ulonglong2 xm = ld2(&ST[e * 448 + 192 + 32 * c + k]);
                    ulonglong2 xr = ld2(&ST[e * 448 + 352 + 32 * c + k]);
                    ffma2(pv[c][e], xm.x, pw.x); ffma2(pv[c][e], xm.y, pw.y);
                    ffma2(rv[c][e], xr.x, rw.x); ffma2(rv[c][e], xr.y, rw.y);
                }
            }
        }
#pragma unroll
        for (int e = 0; e < EB_E; e++) {
            int eg = eb + e;
            if (eg < n_act) {
                float* oe = out_edge + (size_t)eg * DIMX;
                oe[l] = fmaf(fps[0][e], fw[0][e], frs[0][e]);
                oe[32 + l] = fmaf(fps[1][e], fw[1][e], frs[1][e]);
#pragma unroll
                for (int c = 0; c < 3; c++)
                    oe[64 + 3 * l + c] = fmaf(hadd2(pv[c][e]), fw[2][e], hadd2(rv[c][e]));
            }
        }
        __syncwarp();
    }
}

// ===================== K3: hid = silu(lat_in @ W_lat1) =====================
// 384 threads, 12 warps, EPW=8, blockIdx.y in {0,1} selects 128 of 256 outputs
#define L1_T 384
#define L1_W 12
#define L1_E 8
#define SMEM_1 ((128*236 + L1_W*L1_E*232) * 4)
__global__ __launch_bounds__(L1_T, 1) void k_lat1(const float* __restrict__ W1, int n_act) {
    extern __shared__ float sm[];
    float* WT = sm;
    float* STG = WT + 128 * 236;
    int tid = threadIdx.x;
    int base = blockIdx.y * 128;
    for (int i = tid; i < 232 * 128; i += L1_T) {
        int oo = i % 128, k = i / 128;
        WT[oo * 236 + k] = W1[k * 256 + base + oo];
    }
    __syncthreads();
    int wq = tid >> 5, l = tid & 31;
    float* ST = STG + wq * (L1_E * 232);
    int gw = blockIdx.x * L1_W + wq;
    int stride = gridDim.x * L1_W * L1_E;
    for (int eb = gw * L1_E; eb < n_act; eb += stride) {
#pragma unroll
        for (int e = 0; e < L1_E; e++) {
            int ec = eb + e; if (ec >= n_act) ec = n_act - 1;
            const float* li = g_lat_in + (size_t)ec * 232;
            for (int k = l; k < 232; k += 32) ST[e * 232 + k] = li[k];
        }
        __syncwarp();
        u64 acc[4][L1_E];
#pragma unroll
        for (int m = 0; m < 4; m++)
#pragma unroll
            for (int e = 0; e < L1_E; e++) acc[m][e] = 0ull;
        for (int k = 0; k < 232; k += 4) {
            ulonglong2 w0 = ld2(&WT[l * 236 + k]);
            ulonglong2 w1 = ld2(&WT[(l + 32) * 236 + k]);
            ulonglong2 w2 = ld2(&WT[(l + 64) * 236 + k]);
            ulonglong2 w3 = ld2(&WT[(l + 96) * 236 + k]);
#pragma unroll
            for (int e = 0; e < L1_E; e++) {
                ulonglong2 x = ld2(&ST[e * 232 + k]);
                ffma2(acc[0][e], x.x, w0.x); ffma2(acc[0][e], x.y, w0.y);
                ffma2(acc[1][e], x.x, w1.x); ffma2(acc[1][e], x.y, w1.y);
                ffma2(acc[2][e], x.x, w2.x); ffma2(acc[2][e], x.y, w2.y);
                ffma2(acc[3][e], x.x, w3.x); ffma2(acc[3][e], x.y, w3.y);
            }
        }
#pragma unroll
        for (int e = 0; e < L1_E; e++) {
            int eg = eb + e;
            if (eg < n_act) {
                float* h = g_hid + (size_t)eg * 256 + base;
#pragma unroll
                for (int m = 0; m < 4; m++) {
                    float v = hadd2(acc[m][e]);
                    h[l + 32 * m] = v * sigm(v);
                }
            }
        }
        __syncwarp();
    }
}

// ===================== K4: new_lat = (hid @ W_lat2) * cutoff -> scatter =====================
// 384 threads, 12 warps, EPW=8
#define L2_T 384
#define L2_W 12
#define L2_E 8
#define SMEM_2 ((128*260 + L2_W*L2_E*256) * 4)
__global__ __launch_bounds__(L2_T, 1) void k_lat2(
    const float* __restrict__ W2, const int* __restrict__ act,
    const float* __restrict__ cutoff, float* __restrict__ out_lat, int n_act) {
    extern __shared__ float sm[];
    float* WT = sm;
    float* STG = WT + 128 * 260;
    int tid = threadIdx.x;
    for (int i = tid; i < 256 * 128; i += L2_T)
        WT[(i % 128) * 260 + i / 128] = W2[i];
    __syncthreads();
    int wq = tid >> 5, l = tid & 31;
    float* ST = STG + wq * (L2_E * 256);
    int gw = blockIdx.x * L2_W + wq;
    int stride = gridDim.x * L2_W * L2_E;
    for (int eb = gw * L2_E; eb < n_act; eb += stride) {
#pragma unroll
        for (int e = 0; e < L2_E; e++) {
            int ec = eb + e; if (ec >= n_act) ec = n_act - 1;
            const float* h = g_hid + (size_t)ec * 256;
#pragma unroll
            for (int j = 0; j < 8; j++) ST[e * 256 + l + 32 * j] = h[l + 32 * j];
        }
        __syncwarp();
        u64 acc[4][L2_E];
#pragma unroll
        for (int m = 0; m < 4; m++)
#pragma unroll
            for (int e = 0; e < L2_E; e++) acc[m][e] = 0ull;
        for (int k = 0; k < 256; k += 4) {
            ulonglong2 w0 = ld2(&WT[l * 260 + k]);
            ulonglong2 w1 = ld2(&WT[(l + 32) * 260 + k]);
            ulonglong2 w2 = ld2(&WT[(l + 64) * 260 + k]);
            ulonglong2 w3 = ld2(&WT[(l + 96) * 260 + k]);
#pragma unroll
            for (int e = 0; e < L2_E; e++) {
                ulonglong2 x = ld2(&ST[e * 256 + k]);
                ffma2(acc[0][e], x.x, w0.x); ffma2(acc[0][e], x.y, w0.y);
                ffma2(acc[1][e], x.x, w1.x); ffma2(acc[1][e], x.y, w1.y);
                ffma2(acc[2][e], x.x, w2.x); ffma2(acc[2][e], x.y, w2.y);
                ffma2(acc[3][e], x.x, w3.x); ffma2(acc[3][e], x.y, w3.y);
            }
        }
#pragma unroll
        for (int e = 0; e < L2_E; e++) {
            int eg = eb + e;
            if (eg < n_act) {
                int ae = act[eg];
                float cc = cutoff[ae];
                float* ol = out_lat + (size_t)ae * 128;
#pragma unroll
                for (int m = 0; m < 4; m++) ol[l + 32 * m] = hadd2(acc[m][e]) * cc;
            }
        }
        __syncwarp();
    }
}

// ===================== launcher =====================
extern "C" void kernel_launch(void* const* d_in, const int* in_sizes, int n_in,
                              void* d_out, int out_size) {
    const float* latents   = (const float*)d_in[0];
    const float* node_feat = (const float*)d_in[1];
    const float* onehot    = (const float*)d_in[2];
    const float* edge_feat = (const float*)d_in[3];
    const float* edge_sh   = (const float*)d_in[4];
    const int*   edge_idx  = (const int*)d_in[5];
    const float* cutoff    = (const float*)d_in[6];
    const int*   act       = (const int*)d_in[7];
    const float* n_gs = (const float*)d_in[8];
    const float* n_bs = (const float*)d_in[9];
    const float* n_gv = (const float*)d_in[10];
    const float* e_gs = (const float*)d_in[11];
    const float* e_bs = (const float*)d_in[12];
    const float* e_gv = (const float*)d_in[13];
    const float* lg   = (const float*)d_in[14];
    const float* lb   = (const float*)d_in[15];
    const float* Wa   = (const float*)d_in[16];
    const float* Wb   = (const float*)d_in[17];
    const float* Wc   = (const float*)d_in[18];
    const float* Wd   = (const float*)d_in[19];
    const float* Wps  = (const float*)d_in[20];
    const float* Wpv  = (const float*)d_in[21];
    const float* We   = (const float*)d_in[22];
    const float* W1   = (const float*)d_in[23];
    const float* W2   = (const float*)d_in[24];
    const float* Wrs  = (const float*)d_in[25];
    const float* Wrv  = (const float*)d_in[26];

    int n_nodes = in_sizes[1] / DIMX;
    int n_act   = in_sizes[7];
    int n_edges = in_sizes[6];

    float* out_edge = (float*)d_out;
    float* out_lat  = out_edge + (size_t)n_act * DIMX;

    cudaFuncSetAttribute(k_edge_a, cudaFuncAttributeMaxDynamicSharedMemorySize, SMEM_A);
    cudaFuncSetAttribute(k_edge_b, cudaFuncAttributeMaxDynamicSharedMemorySize, SMEM_B);
    cudaFuncSetAttribute(k_lat1,   cudaFuncAttributeMaxDynamicSharedMemorySize, SMEM_1);
    cudaFuncSetAttribute(k_lat2,   cudaFuncAttributeMaxDynamicSharedMemorySize, SMEM_2);

    cudaMemcpyAsync(out_lat, latents, (size_t)n_edges * 128 * sizeof(float),
                    cudaMemcpyDeviceToDevice, 0);

    int nb1 = (n_nodes * 32 + 255) / 256;
    k_node_norm<<<nb1, 256>>>(node_feat, n_gs, n_bs, n_gv, n_nodes);

    k_edge_a<<<148, EA_T, SMEM_A>>>(edge_feat, edge_sh, edge_idx, act, onehot,
                                    e_gs, e_bs, e_gv, Wa, Wb, Wc, Wd, n_act, n_edges);

    k_edge_b<<<148, EB_T, SMEM_B>>>(latents, edge_feat, act, lg, lb,
                                    We, Wps, Wpv, Wrs, Wrv, out_edge, n_act);

    k_lat1<<<dim3(148, 2), L1_T, SMEM_1>>>(W1, n_act);

    k_lat2<<<148, L2_T, SMEM_2>>>(W2, act, cutoff, out_lat, n_act);
}